// round 6
// baseline (speedup 1.0000x reference)
#include <cuda_runtime.h>
#include <cstdint>

#define DIMX     48
#define HID      16
#define CH       8
#define IMG_H    256
#define IMG_W    256
#define HW       65536
#define TILE     32
#define HALO     34
#define NHALO    (HALO*HALO)    /* 1156 */
#define NINNER   (TILE*TILE)    /* 1024 */
#define NTHREADS 256

// A&S 7.1.26 erf: max abs error 1.5e-7 (negligible vs 1e-3 threshold)
__device__ __forceinline__ float erf_approx(float x) {
    float ax = fabsf(x);
    float t  = __frcp_rn(fmaf(0.3275911f, ax, 1.0f));
    float p  = fmaf(t, 1.061405429f, -1.453152027f);
    p = fmaf(t, p, 1.421413741f);
    p = fmaf(t, p, -0.284496736f);
    p = fmaf(t, p, 0.254829592f);
    p = p * t;
    float e = __expf(-ax * ax);
    float r = fmaf(-p, e, 1.0f);
    return (x < 0.0f) ? -r : r;
}

__device__ __forceinline__ float gelu_f(float z) {
    return 0.5f * z * (1.0f + erf_approx(z * 0.70710678118654752f));
}

extern __shared__ float sm[];

__global__ void __launch_bounds__(NTHREADS, 2) dclf_fused_kernel(
    const float* __restrict__ x,   const float* __restrict__ W1,  const float* __restrict__ b1,
    const float* __restrict__ gam, const float* __restrict__ bet,
    const float* __restrict__ dww, const float* __restrict__ dwb,
    const float* __restrict__ pww, const float* __restrict__ pwb,
    const float* __restrict__ W2,  const float* __restrict__ b2,
    float* __restrict__ out)
{
    // ---- SMEM carve (all segments 16B aligned) ----
    float* sW1  = sm;            // 768  [k*16+j]
    float* sb1  = sW1  + 768;    // 16
    float* sGa  = sb1  + 16;     // 8
    float* sBe  = sGa  + 8;      // 8
    float* sDwT = sBe  + 8;      // 72  [tap*8 + c]
    float* sDwB = sDwT + 72;     // 8
    float* sPw  = sDwB + 8;      // 64  [co*8 + ci]
    float* sPwB = sPw  + 64;     // 8
    float* sW2t = sPwB + 8;      // 384 [d*8 + c]
    float* sb2  = sW2t + 384;    // 48
    float4* sNa  = (float4*)(sb2 + 48);   // 1156 (n ch0..3)
    float4* sNb  = sNa + NHALO;           // 1156 (n ch4..7)
    float4* sX1a = sNb + NHALO;           // 1024 (x1 ch0..3)
    float4* sX1b = sX1a + NINNER;         // 1024 (x1 ch4..7)

    const int tid = threadIdx.x;
    const int bx = blockIdx.x, by = blockIdx.y, bb = blockIdx.z;

    // ---- load weights ----
    for (int i = tid; i < 768; i += NTHREADS) sW1[i] = W1[i];
    if (tid < 16) sb1[tid] = b1[tid];
    if (tid < 8) { sGa[tid] = gam[tid]; sBe[tid] = bet[tid]; sDwB[tid] = dwb[tid]; sPwB[tid] = pwb[tid]; }
    if (tid < 72) sDwT[(tid % 9) * 8 + tid / 9] = dww[tid];       // dww[c][ky][kx] -> [tap][c]
    if (tid < 64) sPw[tid] = pww[tid];                            // [co][ci]
    for (int i = tid; i < 384; i += NTHREADS)
        sW2t[(i % 48) * 8 + (i / 48)] = W2[i];                    // W2[c][d] -> [d][c]
    if (tid < 48) sb2[tid] = b2[tid];
    __syncthreads();

    const int y0 = by * TILE - 1;
    const int x0 = bx * TILE - 1;
    const float* xb = x + (size_t)bb * ((size_t)HW * DIMX);

    // ---- Stage A: GEMM1 + gelu(gelu()) + LN over halo region ----
    for (int q = tid; q < NHALO; q += NTHREADS) {
        int qy = q / HALO, qx = q - qy * HALO;
        int gy = y0 + qy, gx = x0 + qx;
        bool inimg = (gy >= 0) && (gy < IMG_H) && (gx >= 0) && (gx < IMG_W);
        float4 na = make_float4(0.f, 0.f, 0.f, 0.f);
        float4 nb = make_float4(0.f, 0.f, 0.f, 0.f);
        if (inimg) {
            const float4* xp4 = (const float4*)(xb + (size_t)(gy * IMG_W + gx) * DIMX);
            float acc[HID];
            #pragma unroll
            for (int j = 0; j < HID; j++) acc[j] = sb1[j];
            #pragma unroll 3
            for (int i = 0; i < 12; i++) {
                float4 xv = xp4[i];
                const float* wr = &sW1[i * 64];
                #pragma unroll
                for (int j = 0; j < HID; j++) acc[j] = fmaf(xv.x, wr[j],      acc[j]);
                #pragma unroll
                for (int j = 0; j < HID; j++) acc[j] = fmaf(xv.y, wr[16 + j], acc[j]);
                #pragma unroll
                for (int j = 0; j < HID; j++) acc[j] = fmaf(xv.z, wr[32 + j], acc[j]);
                #pragma unroll
                for (int j = 0; j < HID; j++) acc[j] = fmaf(xv.w, wr[48 + j], acc[j]);
            }
            float t8[HID];
            #pragma unroll
            for (int j = 0; j < HID; j++) t8[j] = gelu_f(gelu_f(acc[j]));
            // LayerNorm over channels 8..15
            float s = 0.f;
            #pragma unroll
            for (int j = 8; j < 16; j++) s += t8[j];
            float m = s * 0.125f;
            float v = 0.f;
            #pragma unroll
            for (int j = 8; j < 16; j++) { float d = t8[j] - m; v = fmaf(d, d, v); }
            float r = rsqrtf(fmaf(v, 0.125f, 1e-5f));
            float nv[CH];
            #pragma unroll
            for (int j = 0; j < CH; j++) nv[j] = fmaf((t8[8 + j] - m) * r, sGa[j], sBe[j]);
            na = make_float4(nv[0], nv[1], nv[2], nv[3]);
            nb = make_float4(nv[4], nv[5], nv[6], nv[7]);
            if (qy >= 1 && qy <= TILE && qx >= 1 && qx <= TILE) {
                int ip = (qy - 1) * TILE + (qx - 1);
                sX1a[ip] = make_float4(t8[0], t8[1], t8[2], t8[3]);
                sX1b[ip] = make_float4(t8[4], t8[5], t8[6], t8[7]);
            }
        }
        sNa[q] = na;
        sNb[q] = nb;
    }
    __syncthreads();

    // ---- Stage B: dw 3x3 + pw 1x1 + gate + GEMM2 + strided NCHW store ----
    float* outb = out + (size_t)bb * ((size_t)DIMX * HW);
    #pragma unroll 1
    for (int rr = 0; rr < NINNER / NTHREADS; rr++) {
        int ip = rr * NTHREADS + tid;
        int py = ip >> 5, px = ip & 31;

        float4 spa = make_float4(0.f, 0.f, 0.f, 0.f);
        float4 spb = make_float4(0.f, 0.f, 0.f, 0.f);
        int hpc = (py + 1) * HALO + (px + 1);
        float4 ca = sNa[hpc], cb = sNb[hpc];
        #pragma unroll
        for (int dy = 0; dy < 3; dy++) {
            #pragma unroll
            for (int dx = 0; dx < 3; dx++) {
                int hp = (py + dy) * HALO + (px + dx);
                float4 a  = sNa[hp];
                float4 b4 = sNb[hp];
                const float4* wt = (const float4*)&sDwT[(dy * 3 + dx) * 8];
                float4 wa = wt[0], wb = wt[1];
                spa.x = fmaf(a.x,  wa.x, spa.x);
                spa.y = fmaf(a.y,  wa.y, spa.y);
                spa.z = fmaf(a.z,  wa.z, spa.z);
                spa.w = fmaf(a.w,  wa.w, spa.w);
                spb.x = fmaf(b4.x, wb.x, spb.x);
                spb.y = fmaf(b4.y, wb.y, spb.y);
                spb.z = fmaf(b4.z, wb.z, spb.z);
                spb.w = fmaf(b4.w, wb.w, spb.w);
            }
        }
        spa.x += sDwB[0]; spa.y += sDwB[1]; spa.z += sDwB[2]; spa.w += sDwB[3];
        spb.x += sDwB[4]; spb.y += sDwB[5]; spb.z += sDwB[6]; spb.w += sDwB[7];

        float chv[CH];
        #pragma unroll
        for (int co = 0; co < CH; co++) {
            const float4* pw4 = (const float4*)&sPw[co * 8];
            float4 pa = pw4[0], pb = pw4[1];
            chv[co] = sPwB[co]
                + ca.x * pa.x + ca.y * pa.y + ca.z * pa.z + ca.w * pa.w
                + cb.x * pb.x + cb.y * pb.y + cb.z * pb.z + cb.w * pb.w;
        }

        float4 x1a = sX1a[ip], x1b = sX1b[ip];
        float g0 = x1a.x * (spa.x * chv[0]);
        float g1 = x1a.y * (spa.y * chv[1]);
        float g2 = x1a.z * (spa.z * chv[2]);
        float g3 = x1a.w * (spa.w * chv[3]);
        float g4 = x1b.x * (spb.x * chv[4]);
        float g5 = x1b.y * (spb.y * chv[5]);
        float g6 = x1b.z * (spb.z * chv[6]);
        float g7 = x1b.w * (spb.w * chv[7]);

        float* op = outb + (size_t)((y0 + 1 + py) * IMG_W + (x0 + 1 + px));
        #pragma unroll 8
        for (int d = 0; d < DIMX; d++) {
            const float4* w4 = (const float4*)&sW2t[d * 8];
            float4 wa2 = w4[0], wb2 = w4[1];
            float v = sb2[d]
                + g0 * wa2.x + g1 * wa2.y + g2 * wa2.z + g3 * wa2.w
                + g4 * wb2.x + g5 * wb2.y + g6 * wb2.z + g7 * wb2.w;
            op[(size_t)d * HW] = v;
        }
    }
}

extern "C" void kernel_launch(void* const* d_in, const int* in_sizes, int n_in,
                              void* d_out, int out_size) {
    (void)in_sizes; (void)n_in; (void)out_size;
    const float* x   = (const float*)d_in[0];
    const float* W1  = (const float*)d_in[1];
    const float* b1  = (const float*)d_in[2];
    const float* gam = (const float*)d_in[3];
    const float* bet = (const float*)d_in[4];
    const float* dww = (const float*)d_in[5];
    const float* dwb = (const float*)d_in[6];
    const float* pww = (const float*)d_in[7];
    const float* pwb = (const float*)d_in[8];
    const float* W2  = (const float*)d_in[9];
    const float* b2  = (const float*)d_in[10];
    float* out = (float*)d_out;

    const int smem_bytes = (768 + 16 + 8 + 8 + 72 + 8 + 64 + 8 + 384 + 48) * 4
                         + (NHALO * 2 + NINNER * 2) * 16;   // 75296 B
    cudaFuncSetAttribute(dclf_fused_kernel,
                         cudaFuncAttributeMaxDynamicSharedMemorySize, smem_bytes);

    dim3 grid(IMG_W / TILE, IMG_H / TILE, 16);  // 8 x 8 x B
    dclf_fused_kernel<<<grid, NTHREADS, smem_bytes>>>(
        x, W1, b1, gam, bet, dww, dwb, pww, pwb, W2, b2, out);
}

// round 7
// speedup vs baseline: 1.0925x; 1.0925x over previous
#include <cuda_runtime.h>
#include <cuda_fp16.h>
#include <cstdint>

#define DIMX     48
#define HID      16
#define CH       8
#define IMG_H    256
#define IMG_W    256
#define HW       65536
#define TILE     32
#define HALO     34
#define NHALO    (HALO*HALO)    /* 1156 */
#define NINNER   (TILE*TILE)    /* 1024 */
#define NTHREADS 256
#define STG_STRIDE 13           /* float4 row stride per staged pixel (pad vs 12) */

// A&S 7.1.26 erf: max abs error 1.5e-7
__device__ __forceinline__ float erf_approx(float x) {
    float ax = fabsf(x);
    float t  = __frcp_rn(fmaf(0.3275911f, ax, 1.0f));
    float p  = fmaf(t, 1.061405429f, -1.453152027f);
    p = fmaf(t, p, 1.421413741f);
    p = fmaf(t, p, -0.284496736f);
    p = fmaf(t, p, 0.254829592f);
    p = p * t;
    float e = __expf(-ax * ax);
    float r = fmaf(-p, e, 1.0f);
    return (x < 0.0f) ? -r : r;
}

__device__ __forceinline__ float gelu_f(float z) {
    return 0.5f * z * (1.0f + erf_approx(z * 0.70710678118654752f));
}

__device__ __forceinline__ unsigned pack_h2(float a, float b) {
    __half2 h = __floats2half2_rn(a, b);
    return *reinterpret_cast<unsigned*>(&h);
}
__device__ __forceinline__ float2 unpack_h2(unsigned u) {
    __half2 h = *reinterpret_cast<__half2*>(&u);
    return __half22float2(h);
}

extern __shared__ float sm[];

__global__ void __launch_bounds__(NTHREADS, 2) dclf_fused_kernel(
    const float* __restrict__ x,   const float* __restrict__ W1,  const float* __restrict__ b1,
    const float* __restrict__ gam, const float* __restrict__ bet,
    const float* __restrict__ dww, const float* __restrict__ dwb,
    const float* __restrict__ pww, const float* __restrict__ pwb,
    const float* __restrict__ W2,  const float* __restrict__ b2,
    float* __restrict__ out)
{
    // ---- SMEM carve ----
    float* sW1  = sm;            // 768  [k*16+j]
    float* sb1  = sW1  + 768;    // 16
    float* sGa  = sb1  + 16;     // 8
    float* sBe  = sGa  + 8;      // 8
    float* sDwT = sBe  + 8;      // 72  [tap*8 + c]
    float* sDwB = sDwT + 72;     // 8
    float* sPw  = sDwB + 8;      // 64  [co*8 + ci]
    float* sPwB = sPw  + 64;     // 8
    float* sW2t = sPwB + 8;      // 384 [d*8 + c]
    float* sb2  = sW2t + 384;    // 48           -> 1384 floats total (5536 B, 16B aligned)
    float4* sNa  = (float4*)(sb2 + 48);   // 1156 (n ch0..3)
    float4* sNb  = sNa + NHALO;           // 1156 (n ch4..7)
    uint4*  sX1h = (uint4*)(sNb + NHALO); // 1024 (x1 ch0..7 as fp16)
    float4* sStg = (float4*)(sX1h + NINNER); // 8 warps * 32 px * 13 f4 = 3328

    const int tid  = threadIdx.x;
    const int warp = tid >> 5, lane = tid & 31;
    const int bx = blockIdx.x, by = blockIdx.y, bb = blockIdx.z;

    // ---- load weights ----
    for (int i = tid; i < 768; i += NTHREADS) sW1[i] = W1[i];
    if (tid < 16) sb1[tid] = b1[tid];
    if (tid < 8) { sGa[tid] = gam[tid]; sBe[tid] = bet[tid]; sDwB[tid] = dwb[tid]; sPwB[tid] = pwb[tid]; }
    if (tid < 72) sDwT[(tid % 9) * 8 + tid / 9] = dww[tid];       // dww[c][ky][kx] -> [tap][c]
    if (tid < 64) sPw[tid] = pww[tid];                            // [co][ci]
    for (int i = tid; i < 384; i += NTHREADS)
        sW2t[(i % 48) * 8 + (i / 48)] = W2[i];                    // W2[c][d] -> [d][c]
    if (tid < 48) sb2[tid] = b2[tid];
    __syncthreads();

    const int y0 = by * TILE - 1;
    const int x0 = bx * TILE - 1;
    const float* xb = x + (size_t)bb * ((size_t)HW * DIMX);

    float4* buf = sStg + warp * (32 * STG_STRIDE);

    // ---- Stage A: staged coalesced loads + GEMM1 + gelu(gelu()) + LN ----
    // chunks of 32 halo pixels; warp w handles chunks w, w+8, ... (37 chunks total)
    for (int it = 0; it < 5; ++it) {
        int k = it * 8 + warp;
        if (k > 36) break;
        int q0 = k * 32;
        int qend = min(q0 + 32, NHALO);

        // --- coalesced load of this chunk's x into buf (per-warp) ---
        {
            int r0 = q0 / HALO, r1 = (qend - 1) / HALO;
            #pragma unroll 1
            for (int r = r0; r <= r1; ++r) {
                int gy = y0 + r;
                if ((unsigned)gy < (unsigned)IMG_H) {
                    int qs = max(q0, r * HALO), qe = min(qend, r * HALO + HALO);
                    int gxs = x0 + (qs - r * HALO);
                    int gxe = x0 + (qe - r * HALO);
                    int cs = max(gxs, 0), ce = min(gxe, IMG_W);
                    if (ce > cs) {
                        int bofs = (qs - q0) + (cs - gxs);
                        const float4* gp = (const float4*)(xb + ((size_t)gy * IMG_W + cs) * DIMX);
                        int nf = (ce - cs) * 12;
                        for (int t = lane; t < nf; t += 32)
                            buf[(bofs + t / 12) * STG_STRIDE + (t % 12)] = gp[t];
                    }
                }
            }
        }
        __syncwarp();

        // --- compute this chunk ---
        int q = q0 + lane;
        if (q < qend) {
            int qy = q / HALO, qx = q - qy * HALO;
            int gy = y0 + qy, gx = x0 + qx;
            bool inimg = (gy >= 0) && (gy < IMG_H) && (gx >= 0) && (gx < IMG_W);
            float4 na = make_float4(0.f, 0.f, 0.f, 0.f);
            float4 nb = make_float4(0.f, 0.f, 0.f, 0.f);
            if (inimg) {
                const float4* xp4 = buf + lane * STG_STRIDE;
                float acc[HID];
                #pragma unroll
                for (int j = 0; j < HID; j++) acc[j] = sb1[j];
                #pragma unroll 3
                for (int i = 0; i < 12; i++) {
                    float4 xv = xp4[i];
                    const float* wr = &sW1[i * 64];
                    #pragma unroll
                    for (int j = 0; j < HID; j++) acc[j] = fmaf(xv.x, wr[j],      acc[j]);
                    #pragma unroll
                    for (int j = 0; j < HID; j++) acc[j] = fmaf(xv.y, wr[16 + j], acc[j]);
                    #pragma unroll
                    for (int j = 0; j < HID; j++) acc[j] = fmaf(xv.z, wr[32 + j], acc[j]);
                    #pragma unroll
                    for (int j = 0; j < HID; j++) acc[j] = fmaf(xv.w, wr[48 + j], acc[j]);
                }
                float t8[HID];
                #pragma unroll
                for (int j = 0; j < HID; j++) t8[j] = gelu_f(gelu_f(acc[j]));
                // LayerNorm over channels 8..15
                float s = 0.f;
                #pragma unroll
                for (int j = 8; j < 16; j++) s += t8[j];
                float m = s * 0.125f;
                float v = 0.f;
                #pragma unroll
                for (int j = 8; j < 16; j++) { float d = t8[j] - m; v = fmaf(d, d, v); }
                float r = rsqrtf(fmaf(v, 0.125f, 1e-5f));
                float nv[CH];
                #pragma unroll
                for (int j = 0; j < CH; j++) nv[j] = fmaf((t8[8 + j] - m) * r, sGa[j], sBe[j]);
                na = make_float4(nv[0], nv[1], nv[2], nv[3]);
                nb = make_float4(nv[4], nv[5], nv[6], nv[7]);
                if (qy >= 1 && qy <= TILE && qx >= 1 && qx <= TILE) {
                    int ip = (qy - 1) * TILE + (qx - 1);
                    uint4 u;
                    u.x = pack_h2(t8[0], t8[1]);
                    u.y = pack_h2(t8[2], t8[3]);
                    u.z = pack_h2(t8[4], t8[5]);
                    u.w = pack_h2(t8[6], t8[7]);
                    sX1h[ip] = u;
                }
            }
            sNa[q] = na;
            sNb[q] = nb;
        }
        __syncwarp();
    }
    __syncthreads();

    // ---- Stage B: 4-pixel column strips; dw 3x3 + pw + gate, then batched GEMM2 ----
    const int px = tid & 31;
    const int sy = tid >> 5;            // strip row group 0..7, rows sy*4 .. sy*4+3
    float* outb = out + (size_t)bb * ((size_t)DIMX * HW);

    float g[32];
    #pragma unroll
    for (int r = 0; r < 4; ++r) {
        int py = sy * 4 + r;
        float4 spa = make_float4(0.f, 0.f, 0.f, 0.f);
        float4 spb = make_float4(0.f, 0.f, 0.f, 0.f);
        float4 ca, cb;
        #pragma unroll
        for (int dy = 0; dy < 3; dy++) {
            #pragma unroll
            for (int dx = 0; dx < 3; dx++) {
                int hp = (py + dy) * HALO + (px + dx);
                float4 a  = sNa[hp];
                float4 b4 = sNb[hp];
                if (dy == 1 && dx == 1) { ca = a; cb = b4; }
                const float4* wt = (const float4*)&sDwT[(dy * 3 + dx) * 8];
                float4 wa = wt[0], wb = wt[1];
                spa.x = fmaf(a.x,  wa.x, spa.x);
                spa.y = fmaf(a.y,  wa.y, spa.y);
                spa.z = fmaf(a.z,  wa.z, spa.z);
                spa.w = fmaf(a.w,  wa.w, spa.w);
                spb.x = fmaf(b4.x, wb.x, spb.x);
                spb.y = fmaf(b4.y, wb.y, spb.y);
                spb.z = fmaf(b4.z, wb.z, spb.z);
                spb.w = fmaf(b4.w, wb.w, spb.w);
            }
        }
        spa.x += sDwB[0]; spa.y += sDwB[1]; spa.z += sDwB[2]; spa.w += sDwB[3];
        spb.x += sDwB[4]; spb.y += sDwB[5]; spb.z += sDwB[6]; spb.w += sDwB[7];

        float chv[CH];
        #pragma unroll
        for (int co = 0; co < CH; co++) {
            const float4* pw4 = (const float4*)&sPw[co * 8];
            float4 pa = pw4[0], pb = pw4[1];
            chv[co] = sPwB[co]
                + ca.x * pa.x + ca.y * pa.y + ca.z * pa.z + ca.w * pa.w
                + cb.x * pb.x + cb.y * pb.y + cb.z * pb.z + cb.w * pb.w;
        }

        uint4 u = sX1h[py * TILE + px];
        float2 x01 = unpack_h2(u.x), x23 = unpack_h2(u.y);
        float2 x45 = unpack_h2(u.z), x67 = unpack_h2(u.w);

        g[r * 8 + 0] = x01.x * (spa.x * chv[0]);
        g[r * 8 + 1] = x01.y * (spa.y * chv[1]);
        g[r * 8 + 2] = x23.x * (spa.z * chv[2]);
        g[r * 8 + 3] = x23.y * (spa.w * chv[3]);
        g[r * 8 + 4] = x45.x * (spb.x * chv[4]);
        g[r * 8 + 5] = x45.y * (spb.y * chv[5]);
        g[r * 8 + 6] = x67.x * (spb.z * chv[6]);
        g[r * 8 + 7] = x67.y * (spb.w * chv[7]);
    }

    // batched GEMM2: one W2 pass serves all 4 pixels of the strip
    float* outp = outb + (size_t)((y0 + 1 + sy * 4) * IMG_W + (x0 + 1 + px));
    #pragma unroll 4
    for (int d = 0; d < DIMX; d++) {
        const float4* w4 = (const float4*)&sW2t[d * 8];
        float4 wa2 = w4[0], wb2 = w4[1];
        float bias = sb2[d];
        float* od = outp + (size_t)d * HW;
        #pragma unroll
        for (int r = 0; r < 4; ++r) {
            const float* gr = &g[r * 8];
            float v = bias
                + gr[0] * wa2.x + gr[1] * wa2.y + gr[2] * wa2.z + gr[3] * wa2.w
                + gr[4] * wb2.x + gr[5] * wb2.y + gr[6] * wb2.z + gr[7] * wb2.w;
            od[r * IMG_W] = v;
        }
    }
}

extern "C" void kernel_launch(void* const* d_in, const int* in_sizes, int n_in,
                              void* d_out, int out_size) {
    (void)in_sizes; (void)n_in; (void)out_size;
    const float* x   = (const float*)d_in[0];
    const float* W1  = (const float*)d_in[1];
    const float* b1  = (const float*)d_in[2];
    const float* gam = (const float*)d_in[3];
    const float* bet = (const float*)d_in[4];
    const float* dww = (const float*)d_in[5];
    const float* dwb = (const float*)d_in[6];
    const float* pww = (const float*)d_in[7];
    const float* pwb = (const float*)d_in[8];
    const float* W2  = (const float*)d_in[9];
    const float* b2  = (const float*)d_in[10];
    float* out = (float*)d_out;

    const int smem_bytes = 1384 * 4                      // weights
                         + NHALO * 2 * 16                // sNa + sNb
                         + NINNER * 16                   // sX1h (fp16 packed)
                         + 8 * 32 * STG_STRIDE * 16;     // staging  -> 112160 B
    cudaFuncSetAttribute(dclf_fused_kernel,
                         cudaFuncAttributeMaxDynamicSharedMemorySize, smem_bytes);

    dim3 grid(IMG_W / TILE, IMG_H / TILE, 16);  // 8 x 8 x B
    dclf_fused_kernel<<<grid, NTHREADS, smem_bytes>>>(
        x, W1, b1, gam, bet, dww, dwb, pww, pwb, W2, b2, out);
}

// round 8
// speedup vs baseline: 1.4738x; 1.3490x over previous
#include <cuda_runtime.h>
#include <cuda_fp16.h>
#include <cstdint>

#define DIMX     48
#define HID      16
#define CH       8
#define IMG_H    256
#define IMG_W    256
#define HW       65536
#define TILE     32
#define HALO     34
#define NHALO    (HALO*HALO)    /* 1156 */
#define NINNER   (TILE*TILE)    /* 1024 */
#define NTHREADS 256
#define STG_STRIDE 13           /* float4 row stride per staged pixel */

typedef unsigned long long u64;

// ---- packed f32x2 helpers (sm_103a FFMA2 path; ptxas never emits these from C++) ----
__device__ __forceinline__ u64 f2pack(float lo, float hi) {
    u64 r; asm("mov.b64 %0,{%1,%2};" : "=l"(r) : "f"(lo), "f"(hi)); return r;
}
__device__ __forceinline__ u64 f2bcast(float v) {
    u64 r; asm("mov.b64 %0,{%1,%1};" : "=l"(r) : "f"(v)); return r;
}
__device__ __forceinline__ void f2unpack(u64 v, float& lo, float& hi) {
    asm("mov.b64 {%0,%1},%2;" : "=f"(lo), "=f"(hi) : "l"(v));
}
__device__ __forceinline__ u64 f2fma(u64 a, u64 b, u64 c) {
    u64 d; asm("fma.rn.f32x2 %0,%1,%2,%3;" : "=l"(d) : "l"(a), "l"(b), "l"(c)); return d;
}
__device__ __forceinline__ u64 f2mul(u64 a, u64 b) {
    u64 d; asm("mul.rn.f32x2 %0,%1,%2;" : "=l"(d) : "l"(a), "l"(b)); return d;
}
__device__ __forceinline__ u64 f2add(u64 a, u64 b) {
    u64 d; asm("add.rn.f32x2 %0,%1,%2;" : "=l"(d) : "l"(a), "l"(b)); return d;
}
__device__ __forceinline__ u64 c2(float v) {
    unsigned u = __float_as_uint(v);
    return ((u64)u << 32) | (u64)u;
}

// packed double-value GELU (exact-erf form, A&S 7.1.26 poly; MUFU parts scalar)
__device__ __forceinline__ u64 gelu2(u64 z) {
    u64 arg = f2mul(z, c2(0.70710678118654752f));
    u64 ax  = arg & 0x7FFFFFFF7FFFFFFFULL;
    u64 den = f2fma(ax, c2(0.3275911f), c2(1.0f));
    float d0, d1, t0, t1;
    f2unpack(den, d0, d1);
    asm("rcp.approx.f32 %0,%1;" : "=f"(t0) : "f"(d0));
    asm("rcp.approx.f32 %0,%1;" : "=f"(t1) : "f"(d1));
    u64 t = f2pack(t0, t1);
    u64 p = f2fma(t, c2(1.061405429f), c2(-1.453152027f));
    p = f2fma(t, p, c2(1.421413741f));
    p = f2fma(t, p, c2(-0.284496736f));
    p = f2fma(t, p, c2(0.254829592f));
    p = f2mul(p, t);
    u64 m = f2mul(ax, ax ^ 0x8000000080000000ULL);   // -ax^2
    m = f2mul(m, c2(1.4426950408889634f));
    float m0, m1, e0, e1;
    f2unpack(m, m0, m1);
    asm("ex2.approx.f32 %0,%1;" : "=f"(e0) : "f"(m0));
    asm("ex2.approx.f32 %0,%1;" : "=f"(e1) : "f"(m1));
    u64 e = f2pack(e0, e1);
    u64 r = f2fma(f2mul(p, e), c2(-1.0f), c2(1.0f));
    u64 erf = r | (arg & 0x8000000080000000ULL);
    u64 h = f2mul(z, c2(0.5f));
    return f2fma(h, erf, h);
}

__device__ __forceinline__ unsigned pack_h2(float a, float b) {
    __half2 h = __floats2half2_rn(a, b);
    return *reinterpret_cast<unsigned*>(&h);
}
__device__ __forceinline__ float2 unpack_h2(unsigned u) {
    __half2 h = *reinterpret_cast<__half2*>(&u);
    return __half22float2(h);
}

extern __shared__ float sm[];

__global__ void __launch_bounds__(NTHREADS, 2) dclf_fused_kernel(
    const float* __restrict__ x,   const float* __restrict__ W1,  const float* __restrict__ b1,
    const float* __restrict__ gam, const float* __restrict__ bet,
    const float* __restrict__ dww, const float* __restrict__ dwb,
    const float* __restrict__ pww, const float* __restrict__ pwb,
    const float* __restrict__ W2,  const float* __restrict__ b2,
    float* __restrict__ out)
{
    // ---- SMEM carve (all segments 16B aligned) ----
    float* sW1  = sm;            // 768  [k*16+j]   (j-pairs natural for f32x2)
    float* sb1  = sW1  + 768;    // 16
    float* sGa  = sb1  + 16;     // 8
    float* sBe  = sGa  + 8;      // 8
    float* sDwT = sBe  + 8;      // 72  [tap*8 + c]
    float* sDwB = sDwT + 72;     // 8
    float* sPwT = sDwB + 8;      // 64  [ci*8 + co]  (transposed, co-pairs packed)
    float* sPwB = sPwT + 64;     // 8
    float* sW2p = sPwB + 8;      // 384 [dpair*16 + c*2 + h] : f2{W2[c][2dp],W2[c][2dp+1]}
    float* sb2  = sW2p + 384;    // 48
    ulonglong2* sNa  = (ulonglong2*)(sb2 + 48);  // 1156 (n ch0..3 as 2x f2)
    ulonglong2* sNb  = sNa + NHALO;              // 1156 (n ch4..7)
    uint4*      sX1h = (uint4*)(sNb + NHALO);    // 1024 (x1 ch0..7 fp16)
    float4*     sStg = (float4*)(sX1h + NINNER); // 8 warps * 32 px * 13 f4

    const int tid  = threadIdx.x;
    const int warp = tid >> 5, lane = tid & 31;
    const int bx = blockIdx.x, by = blockIdx.y, bb = blockIdx.z;

    // ---- load / relayout weights ----
    for (int i = tid; i < 768; i += NTHREADS) sW1[i] = W1[i];
    if (tid < 16) sb1[tid] = b1[tid];
    if (tid < 8) { sGa[tid] = gam[tid]; sBe[tid] = bet[tid]; sDwB[tid] = dwb[tid]; sPwB[tid] = pwb[tid]; }
    if (tid < 72) sDwT[(tid % 9) * 8 + tid / 9] = dww[tid];        // [c][3][3] -> [tap][c]
    if (tid < 64) sPwT[(tid % 8) * 8 + tid / 8] = pww[tid];        // [co][ci] -> [ci][co]
    for (int i = tid; i < 384; i += NTHREADS) {
        int dp = i >> 4, rem = i & 15, c = rem >> 1, h = rem & 1;
        sW2p[i] = W2[c * DIMX + dp * 2 + h];                       // W2[c][d] -> [dp][c-pairs]
    }
    if (tid < 48) sb2[tid] = b2[tid];
    __syncthreads();

    const int y0 = by * TILE - 1;
    const int x0 = bx * TILE - 1;
    const float* xb = x + (size_t)bb * ((size_t)HW * DIMX);

    float4* buf = sStg + warp * (32 * STG_STRIDE);

    // ---- Stage A: staged coalesced loads + packed GEMM1 + gelu2(gelu2) + LN ----
    for (int it = 0; it < 5; ++it) {
        int k = it * 8 + warp;
        if (k > 36) break;
        int q0 = k * 32;
        int qend = min(q0 + 32, NHALO);

        // coalesced chunk load
        {
            int r0 = q0 / HALO, r1 = (qend - 1) / HALO;
            #pragma unroll 1
            for (int r = r0; r <= r1; ++r) {
                int gy = y0 + r;
                if ((unsigned)gy < (unsigned)IMG_H) {
                    int qs = max(q0, r * HALO), qe = min(qend, r * HALO + HALO);
                    int gxs = x0 + (qs - r * HALO);
                    int gxe = x0 + (qe - r * HALO);
                    int cs = max(gxs, 0), ce = min(gxe, IMG_W);
                    if (ce > cs) {
                        int bofs = (qs - q0) + (cs - gxs);
                        const float4* gp = (const float4*)(xb + ((size_t)gy * IMG_W + cs) * DIMX);
                        int nf = (ce - cs) * 12;
                        for (int t = lane; t < nf; t += 32)
                            buf[(bofs + t / 12) * STG_STRIDE + (t % 12)] = gp[t];
                    }
                }
            }
        }
        __syncwarp();

        int q = q0 + lane;
        if (q < qend) {
            int qy = q / HALO, qx = q - qy * HALO;
            int gy = y0 + qy, gx = x0 + qx;
            bool inimg = (gy >= 0) && (gy < IMG_H) && (gx >= 0) && (gx < IMG_W);
            ulonglong2 na = make_ulonglong2(0ULL, 0ULL);
            ulonglong2 nb = make_ulonglong2(0ULL, 0ULL);
            if (inimg) {
                const float4* xp4 = buf + lane * STG_STRIDE;
                u64 acc[8];
                #pragma unroll
                for (int jj = 0; jj < 8; jj++) acc[jj] = ((const u64*)sb1)[jj];
                #pragma unroll 3
                for (int i = 0; i < 12; i++) {
                    float4 xv = xp4[i];
                    const ulonglong2* wr = (const ulonglong2*)&sW1[i * 64];
                    u64 xb2;
                    xb2 = f2bcast(xv.x);
                    #pragma unroll
                    for (int jj = 0; jj < 4; jj++) { ulonglong2 w = wr[jj];      acc[2*jj] = f2fma(xb2, w.x, acc[2*jj]); acc[2*jj+1] = f2fma(xb2, w.y, acc[2*jj+1]); }
                    xb2 = f2bcast(xv.y);
                    #pragma unroll
                    for (int jj = 0; jj < 4; jj++) { ulonglong2 w = wr[4 + jj];  acc[2*jj] = f2fma(xb2, w.x, acc[2*jj]); acc[2*jj+1] = f2fma(xb2, w.y, acc[2*jj+1]); }
                    xb2 = f2bcast(xv.z);
                    #pragma unroll
                    for (int jj = 0; jj < 4; jj++) { ulonglong2 w = wr[8 + jj];  acc[2*jj] = f2fma(xb2, w.x, acc[2*jj]); acc[2*jj+1] = f2fma(xb2, w.y, acc[2*jj+1]); }
                    xb2 = f2bcast(xv.w);
                    #pragma unroll
                    for (int jj = 0; jj < 4; jj++) { ulonglong2 w = wr[12 + jj]; acc[2*jj] = f2fma(xb2, w.x, acc[2*jj]); acc[2*jj+1] = f2fma(xb2, w.y, acc[2*jj+1]); }
                }
                #pragma unroll
                for (int jj = 0; jj < 8; jj++) acc[jj] = gelu2(gelu2(acc[jj]));

                // LayerNorm over channels 8..15 (= acc[4..7])
                u64 s2 = f2add(f2add(acc[4], acc[5]), f2add(acc[6], acc[7]));
                float sa, sb_; f2unpack(s2, sa, sb_);
                float mmean = (sa + sb_) * 0.125f;
                u64 m2 = f2bcast(mmean);
                u64 d2[4];
                u64 v2 = 0ULL;
                #pragma unroll
                for (int jj = 0; jj < 4; jj++) { d2[jj] = f2fma(m2, c2(-1.0f), acc[4 + jj]); v2 = f2fma(d2[jj], d2[jj], v2); }
                float va, vb; f2unpack(v2, va, vb);
                float rstd = rsqrtf(fmaf(va + vb, 0.125f, 1e-5f));
                u64 r2 = f2bcast(rstd);
                u64 n2[4];
                #pragma unroll
                for (int jj = 0; jj < 4; jj++)
                    n2[jj] = f2fma(f2mul(d2[jj], r2), ((const u64*)sGa)[jj], ((const u64*)sBe)[jj]);
                na = make_ulonglong2(n2[0], n2[1]);
                nb = make_ulonglong2(n2[2], n2[3]);

                if (qy >= 1 && qy <= TILE && qx >= 1 && qx <= TILE) {
                    int ip = (qy - 1) * TILE + (qx - 1);
                    float a0, a1; uint4 u;
                    f2unpack(acc[0], a0, a1); u.x = pack_h2(a0, a1);
                    f2unpack(acc[1], a0, a1); u.y = pack_h2(a0, a1);
                    f2unpack(acc[2], a0, a1); u.z = pack_h2(a0, a1);
                    f2unpack(acc[3], a0, a1); u.w = pack_h2(a0, a1);
                    sX1h[ip] = u;
                }
            }
            sNa[q] = na;
            sNb[q] = nb;
        }
        __syncwarp();
    }
    __syncthreads();

    // ---- Stage B: packed dw/pw/gate + packed GEMM2 over 2-pixel halves ----
    const int px = tid & 31;
    const int sy = tid >> 5;
    float* outb = out + (size_t)bb * ((size_t)DIMX * HW);
    const u64* dwbU = (const u64*)sDwB;
    const u64* pwbU = (const u64*)sPwB;
    const u64* sb2U = (const u64*)sb2;

    #pragma unroll
    for (int half = 0; half < 2; ++half) {
        u64 gb[16];   // broadcast-packed gates for 2 pixels x 8 channels
        #pragma unroll
        for (int r2i = 0; r2i < 2; ++r2i) {
            int py = sy * 4 + half * 2 + r2i;
            u64 s0 = dwbU[0], s1 = dwbU[1], s2 = dwbU[2], s3 = dwbU[3];
            u64 ca[4];
            #pragma unroll
            for (int dy = 0; dy < 3; dy++) {
                #pragma unroll
                for (int dx = 0; dx < 3; dx++) {
                    int hp = (py + dy) * HALO + (px + dx);
                    ulonglong2 a2 = sNa[hp];
                    ulonglong2 b2v = sNb[hp];
                    if (dy == 1 && dx == 1) { ca[0] = a2.x; ca[1] = a2.y; ca[2] = b2v.x; ca[3] = b2v.y; }
                    const ulonglong2* wt = (const ulonglong2*)&sDwT[(dy * 3 + dx) * 8];
                    ulonglong2 wa = wt[0], wb = wt[1];
                    s0 = f2fma(a2.x,  wa.x, s0);
                    s1 = f2fma(a2.y,  wa.y, s1);
                    s2 = f2fma(b2v.x, wb.x, s2);
                    s3 = f2fma(b2v.y, wb.y, s3);
                }
            }
            // pointwise conv (co-pairs packed)
            u64 chv0 = pwbU[0], chv1 = pwbU[1], chv2 = pwbU[2], chv3 = pwbU[3];
            float n[8];
            f2unpack(ca[0], n[0], n[1]);
            f2unpack(ca[1], n[2], n[3]);
            f2unpack(ca[2], n[4], n[5]);
            f2unpack(ca[3], n[6], n[7]);
            #pragma unroll
            for (int ci = 0; ci < 8; ++ci) {
                u64 nb_ = f2bcast(n[ci]);
                const ulonglong2* pwr = (const ulonglong2*)&sPwT[ci * 8];
                ulonglong2 w0 = pwr[0], w1 = pwr[1];
                chv0 = f2fma(nb_, w0.x, chv0);
                chv1 = f2fma(nb_, w0.y, chv1);
                chv2 = f2fma(nb_, w1.x, chv2);
                chv3 = f2fma(nb_, w1.y, chv3);
            }
            // gate
            uint4 u = sX1h[py * TILE + px];
            float2 f;
            u64 g2v; float ga, gbh;
            f = unpack_h2(u.x); g2v = f2mul(f2pack(f.x, f.y), f2mul(s0, chv0));
            f2unpack(g2v, ga, gbh); gb[r2i*8 + 0] = f2bcast(ga); gb[r2i*8 + 1] = f2bcast(gbh);
            f = unpack_h2(u.y); g2v = f2mul(f2pack(f.x, f.y), f2mul(s1, chv1));
            f2unpack(g2v, ga, gbh); gb[r2i*8 + 2] = f2bcast(ga); gb[r2i*8 + 3] = f2bcast(gbh);
            f = unpack_h2(u.z); g2v = f2mul(f2pack(f.x, f.y), f2mul(s2, chv2));
            f2unpack(g2v, ga, gbh); gb[r2i*8 + 4] = f2bcast(ga); gb[r2i*8 + 5] = f2bcast(gbh);
            f = unpack_h2(u.w); g2v = f2mul(f2pack(f.x, f.y), f2mul(s3, chv3));
            f2unpack(g2v, ga, gbh); gb[r2i*8 + 6] = f2bcast(ga); gb[r2i*8 + 7] = f2bcast(gbh);
        }

        // packed GEMM2: d-pairs, 2 pixels per pass
        float* op0 = outb + (size_t)((y0 + 1 + sy * 4 + half * 2) * IMG_W + (x0 + 1 + px));
        #pragma unroll 6
        for (int dp = 0; dp < 24; ++dp) {
            const ulonglong2* wv = (const ulonglong2*)&sW2p[dp * 16];
            ulonglong2 w0 = wv[0], w1 = wv[1], w2v = wv[2], w3 = wv[3];
            u64 bias2 = sb2U[dp];
            #pragma unroll
            for (int r2i = 0; r2i < 2; ++r2i) {
                const u64* gr = &gb[r2i * 8];
                u64 a = bias2;
                a = f2fma(gr[0], w0.x,  a);
                a = f2fma(gr[1], w0.y,  a);
                a = f2fma(gr[2], w1.x,  a);
                a = f2fma(gr[3], w1.y,  a);
                a = f2fma(gr[4], w2v.x, a);
                a = f2fma(gr[5], w2v.y, a);
                a = f2fma(gr[6], w3.x,  a);
                a = f2fma(gr[7], w3.y,  a);
                float v0, v1; f2unpack(a, v0, v1);
                float* od = op0 + r2i * IMG_W + (size_t)(dp * 2) * HW;
                od[0]  = v0;
                od[HW] = v1;
            }
        }
    }
}

extern "C" void kernel_launch(void* const* d_in, const int* in_sizes, int n_in,
                              void* d_out, int out_size) {
    (void)in_sizes; (void)n_in; (void)out_size;
    const float* x   = (const float*)d_in[0];
    const float* W1  = (const float*)d_in[1];
    const float* b1  = (const float*)d_in[2];
    const float* gam = (const float*)d_in[3];
    const float* bet = (const float*)d_in[4];
    const float* dww = (const float*)d_in[5];
    const float* dwb = (const float*)d_in[6];
    const float* pww = (const float*)d_in[7];
    const float* pwb = (const float*)d_in[8];
    const float* W2  = (const float*)d_in[9];
    const float* b2  = (const float*)d_in[10];
    float* out = (float*)d_out;

    const int smem_bytes = 1384 * 4                      // weights
                         + NHALO * 2 * 16                // sNa + sNb
                         + NINNER * 16                   // sX1h
                         + 8 * 32 * STG_STRIDE * 16;     // staging  -> 112160 B
    cudaFuncSetAttribute(dclf_fused_kernel,
                         cudaFuncAttributeMaxDynamicSharedMemorySize, smem_bytes);

    dim3 grid(IMG_W / TILE, IMG_H / TILE, 16);  // 8 x 8 x B
    dclf_fused_kernel<<<grid, NTHREADS, smem_bytes>>>(
        x, W1, b1, gam, bet, dww, dwb, pww, pwb, W2, b2, out);
}